// round 4
// baseline (speedup 1.0000x reference)
#include <cuda_runtime.h>
#include <cstdint>
#include <cstddef>

#define NN 16384
#define DD 128
#define EE 524288

__device__ float g_pre[(size_t)NN*DD];
__device__ float g_all[(size_t)NN*DD];
__device__ float g_sub[(size_t)NN*DD];
__device__ int g_row[EE];
__device__ int g_col[EE];
__device__ int g_idx64;

__global__ void k_detect(const int* w) {
    __shared__ int any;
    if (threadIdx.x == 0) any = 0;
    __syncthreads();
    if (w[2*threadIdx.x + 1] != 0) atomicOr(&any, 1);
    __syncthreads();
    if (threadIdx.x == 0) g_idx64 = any ? 0 : 1;
}

__global__ void k_init(const int* __restrict__ w, const float* __restrict__ X,
                       float* __restrict__ out) {
    int t = blockIdx.x * blockDim.x + threadIdx.x;  // 0..EE-1
    if (t < EE) {
        int r, c;
        if (g_idx64) { r = w[2*t]; c = w[2*EE + 2*t]; }
        else         { r = w[t];   c = w[EE + t]; }
        g_row[t] = r; g_col[t] = c;
    }
    // EE == NN*DD/4: copy X -> pre, write out[:,0:128] = 2X
    float4 x = ((const float4*)X)[t];
    ((float4*)g_pre)[t] = x;
    int node = t >> 5, c4 = (t & 31) << 2;
    float4 y = make_float4(2.f*x.x, 2.f*x.y, 2.f*x.z, 2.f*x.w);
    *(float4*)(out + (size_t)node*512 + c4) = y;
}

__global__ void k_zero() {
    int t = blockIdx.x * blockDim.x + threadIdx.x;
    ((float4*)g_sub)[t] = make_float4(0.f, 0.f, 0.f, 0.f);
}

__global__ void k_scatter(const float* __restrict__ vals) {
    int t = blockIdx.x * blockDim.x + threadIdx.x;  // EE*32 threads
    int e = t >> 5, d4 = (t & 31) << 2;
    float v = vals[e];
    int r = g_row[e], c = g_col[e];
    float4 p = *(const float4*)(g_pre + (size_t)c*DD + d4);
    float* dst = g_sub + (size_t)r*DD + d4;
    atomicAdd(dst + 0, v*p.x);
    atomicAdd(dst + 1, v*p.y);
    atomicAdd(dst + 2, v*p.z);
    atomicAdd(dst + 3, v*p.w);
}

#define BM 64
#define BK 32
#define ASTR 68   // padded k-major row stride (floats); 272B, 16B aligned, 4-way STS max
__global__ void __launch_bounds__(256, 2) k_gemm(const float* __restrict__ A) {
    __shared__ __align__(16) float As[2][BK][ASTR];   // ~17 KB
    __shared__ __align__(16) float Bs[2][BK][DD];     // 32 KB
    const float* B = g_pre;
    int t = threadIdx.x;
    int rb = blockIdx.x * BM;
    int tx = t & 31, ty = t >> 5;
    // acc[i2][j]: packed f32x2 = rows (ty*8+2*i2, +1), col tx*4+j
    unsigned long long acc[4][4];
#pragma unroll
    for (int i = 0; i < 4; i++)
#pragma unroll
        for (int j = 0; j < 4; j++) acc[i][j] = 0ull;

#pragma unroll
    for (int l = 0; l < 2; l++) {
        int li = t + l*256, r = li >> 3, k4 = (li & 7) << 2;
        float4 v = *(const float4*)(A + (size_t)(rb + r)*NN + k4);
        As[0][k4+0][r] = v.x; As[0][k4+1][r] = v.y;
        As[0][k4+2][r] = v.z; As[0][k4+3][r] = v.w;
    }
#pragma unroll
    for (int l = 0; l < 4; l++) {
        int li = t + l*256, bk = li >> 5, bc = (li & 31) << 2;
        *(float4*)&Bs[0][bk][bc] = *(const float4*)(B + (size_t)bk*DD + bc);
    }
    __syncthreads();

    int buf = 0;
    float4 ra[2], rv[4];
    for (int kt = 0; kt < NN/BK; kt++) {
        int k0n = (kt + 1) * BK;
        if (k0n < NN) {
#pragma unroll
            for (int l = 0; l < 2; l++) {
                int li = t + l*256, r = li >> 3, k4 = (li & 7) << 2;
                ra[l] = *(const float4*)(A + (size_t)(rb + r)*NN + k0n + k4);
            }
#pragma unroll
            for (int l = 0; l < 4; l++) {
                int li = t + l*256, bk = li >> 5, bc = (li & 31) << 2;
                rv[l] = *(const float4*)(B + (size_t)(k0n + bk)*DD + bc);
            }
        }
#pragma unroll
        for (int kk = 0; kk < BK; kk++) {
            const float* arow = &As[buf][kk][ty*8];
            ulonglong2 a0 = *(const ulonglong2*)arow;        // rows 0-1, 2-3
            ulonglong2 a1 = *(const ulonglong2*)(arow + 4);  // rows 4-5, 6-7
            unsigned long long aa[4] = {a0.x, a0.y, a1.x, a1.y};
            float4 b = *(float4*)&Bs[buf][kk][tx*4];
            unsigned long long bb[4];
            asm("mov.b64 %0, {%1, %1};" : "=l"(bb[0]) : "f"(b.x));
            asm("mov.b64 %0, {%1, %1};" : "=l"(bb[1]) : "f"(b.y));
            asm("mov.b64 %0, {%1, %1};" : "=l"(bb[2]) : "f"(b.z));
            asm("mov.b64 %0, {%1, %1};" : "=l"(bb[3]) : "f"(b.w));
#pragma unroll
            for (int i = 0; i < 4; i++)
#pragma unroll
                for (int j = 0; j < 4; j++)
                    asm("fma.rn.f32x2 %0, %1, %2, %0;"
                        : "+l"(acc[i][j]) : "l"(aa[i]), "l"(bb[j]));
        }
        if (k0n < NN) {
#pragma unroll
            for (int l = 0; l < 2; l++) {
                int li = t + l*256, r = li >> 3, k4 = (li & 7) << 2;
                As[buf^1][k4+0][r] = ra[l].x; As[buf^1][k4+1][r] = ra[l].y;
                As[buf^1][k4+2][r] = ra[l].z; As[buf^1][k4+3][r] = ra[l].w;
            }
#pragma unroll
            for (int l = 0; l < 4; l++) {
                int li = t + l*256, bk = li >> 5, bc = (li & 31) << 2;
                *(float4*)&Bs[buf^1][bk][bc] = rv[l];
            }
            __syncthreads();
            buf ^= 1;
        }
    }
#pragma unroll
    for (int i = 0; i < 4; i++) {
        float lo[4], hi[4];
#pragma unroll
        for (int j = 0; j < 4; j++)
            asm("mov.b64 {%0, %1}, %2;" : "=f"(lo[j]), "=f"(hi[j]) : "l"(acc[i][j]));
        *(float4*)(g_all + (size_t)(rb + ty*8 + 2*i    )*DD + tx*4) = make_float4(lo[0],lo[1],lo[2],lo[3]);
        *(float4*)(g_all + (size_t)(rb + ty*8 + 2*i + 1)*DD + tx*4) = make_float4(hi[0],hi[1],hi[2],hi[3]);
    }
}

#define WP 132  // padded row stride (floats), 16B-aligned, bank-safe
__global__ void k_epi(const float* __restrict__ W2, const float* __restrict__ b2,
                      const float* __restrict__ W3, const float* __restrict__ b3,
                      float* __restrict__ out, int colOff) {
    extern __shared__ float sm[];
    float* W2s = sm;                 // 128*WP
    float* W3s = W2s + 128*WP;
    float* as_ = W3s + 128*WP;       // 32*WP
    float* ss_ = as_ + 32*WP;
    float* b2s = ss_ + 32*WP;        // 128
    float* b3s = b2s + 128;
    int t = threadIdx.x;
#pragma unroll
    for (int l = 0; l < 16; l++) {
        int li = t + l*256, o = li >> 5, d = (li & 31) << 2;
        *(float4*)&W2s[o*WP + d] = *(const float4*)&W2[o*128 + d];
        *(float4*)&W3s[o*WP + d] = *(const float4*)&W3[o*128 + d];
    }
    if (t < 128) { b2s[t] = b2[t]; b3s[t] = b3[t]; }
    int base = blockIdx.x * 32;
#pragma unroll
    for (int l = 0; l < 4; l++) {
        int li = t + l*256, nl = li >> 5, d = (li & 31) << 2;
        size_t g = (size_t)(base + nl)*DD + d;
        float4 p = *(const float4*)(g_pre + g);
        float4 a = *(const float4*)(g_all + g);
        float4 s = *(const float4*)(g_sub + g);
        *(float4*)&as_[nl*WP + d] = make_float4(p.x+a.x, p.y+a.y, p.z+a.z, p.w+a.w);
        *(float4*)&ss_[nl*WP + d] = make_float4(p.x*s.x, p.y*s.y, p.z*s.z, p.w*s.w);
    }
    __syncthreads();

    int nl = t >> 3, lane8 = t & 7;
    int node = base + nl;
    float acc2[16], acc3[16];
#pragma unroll
    for (int j = 0; j < 16; j++) { acc2[j] = b2s[lane8 + 8*j]; acc3[j] = b3s[lane8 + 8*j]; }
    for (int d4 = 0; d4 < 32; d4++) {
        float4 a = *(float4*)&as_[nl*WP + d4*4];
        float4 s = *(float4*)&ss_[nl*WP + d4*4];
#pragma unroll
        for (int j = 0; j < 16; j++) {
            int o = lane8 + 8*j;
            float4 w2 = *(float4*)&W2s[o*WP + d4*4];
            float4 w3 = *(float4*)&W3s[o*WP + d4*4];
            acc2[j] += a.x*w2.x + a.y*w2.y + a.z*w2.z + a.w*w2.w;
            acc3[j] += s.x*w3.x + s.y*w3.y + s.z*w3.z + s.w*w3.w;
        }
    }
    float emb[16], ssq = 0.f;
#pragma unroll
    for (int j = 0; j < 16; j++) {
        float h2 = acc2[j], h3 = acc3[j];
        float sg = 1.f / (1.f + __expf(-h2));
        float lr = h3 > 0.f ? h3 : 0.01f * h3;
        float e = sg + lr;
        emb[j] = e; ssq += e * e;
    }
    ssq += __shfl_xor_sync(0xffffffffu, ssq, 1);
    ssq += __shfl_xor_sync(0xffffffffu, ssq, 2);
    ssq += __shfl_xor_sync(0xffffffffu, ssq, 4);
    float inv = 1.f / fmaxf(sqrtf(ssq), 1e-12f);
#pragma unroll
    for (int j = 0; j < 16; j++) {
        int o = lane8 + 8*j;
        g_pre[(size_t)node*DD + o] = emb[j];
        out[(size_t)node*512 + colOff + o] = emb[j] * inv;
    }
}

#define EPI_SMEM ((2*128*WP + 2*32*WP + 2*128) * 4)

extern "C" void kernel_launch(void* const* d_in, const int* in_sizes, int n_in,
                              void* d_out, int out_size) {
    const float* A  = (const float*)d_in[0];
    const int*   si = (const int*)d_in[1];
    const float* sv = (const float*)d_in[2];
    const float* X  = (const float*)d_in[3];
    const float* W2 = (const float*)d_in[4];
    const float* b2 = (const float*)d_in[5];
    const float* W3 = (const float*)d_in[6];
    const float* b3 = (const float*)d_in[7];
    float* out = (float*)d_out;

    cudaFuncSetAttribute(k_epi, cudaFuncAttributeMaxDynamicSharedMemorySize, EPI_SMEM);

    k_detect<<<1, 256>>>(si);
    k_init<<<EE/256, 256>>>(si, X, out);
    for (int k = 0; k < 3; k++) {
        k_zero<<<(NN*DD/4)/256, 256>>>();
        k_scatter<<<(EE*32)/256, 256>>>(sv);
        k_gemm<<<NN/BM, 256>>>(A);
        k_epi<<<NN/32, 256, EPI_SMEM>>>(W2 + k*DD*DD, b2 + k*DD,
                                        W3 + k*DD*DD, b3 + k*DD,
                                        out, (k+1)*DD);
    }
}

// round 10
// speedup vs baseline: 1.5790x; 1.5790x over previous
#include <cuda_runtime.h>
#include <cuda_bf16.h>
#include <cstdint>
#include <cstddef>

#define NN 16384
#define DD 128
#define EE 524288

__device__ float g_pre[(size_t)NN*DD];
__device__ float g_all[(size_t)NN*DD];
__device__ float g_sub[(size_t)NN*DD];
__device__ __nv_bfloat16 g_bT_hi[(size_t)DD*NN];   // [n][k]
__device__ __nv_bfloat16 g_bT_lo[(size_t)DD*NN];
__device__ int g_row[EE];
__device__ int g_col[EE];
__device__ int g_idx64;

__device__ __forceinline__ uint32_t packbf2(float a, float b) {
    __nv_bfloat162 h = __floats2bfloat162_rn(a, b);
    return *(uint32_t*)&h;
}

// word index within a 32-k row for the bf16 pair starting at even k:
// word = s*8 + kw*2 + h   (s = k/16, kw = (k%8)/2, h = (k%16)/8)
#define WIDX(k) ((((k) >> 4) << 3) | ((k) & 6) | (((k) >> 3) & 1))
#define AW 24   // padded words per 32-k row (conflict-free for frag LDS.64)

__device__ __forceinline__ void mma_bf16(float* d, const uint32_t* a, uint32_t b0, uint32_t b1) {
    asm volatile(
        "mma.sync.aligned.m16n8k16.row.col.f32.bf16.bf16.f32 "
        "{%0,%1,%2,%3}, {%4,%5,%6,%7}, {%8,%9}, {%0,%1,%2,%3};"
        : "+f"(d[0]), "+f"(d[1]), "+f"(d[2]), "+f"(d[3])
        : "r"(a[0]), "r"(a[1]), "r"(a[2]), "r"(a[3]), "r"(b0), "r"(b1));
}

// ---------- setup kernels ----------
__global__ void k_detect(const int* w) {
    __shared__ int any;
    if (threadIdx.x == 0) any = 0;
    __syncthreads();
    if (w[2*threadIdx.x + 1] != 0) atomicOr(&any, 1);
    __syncthreads();
    if (threadIdx.x == 0) g_idx64 = any ? 0 : 1;
}

__global__ void k_init(const int* __restrict__ w, const float* __restrict__ X,
                       float* __restrict__ out) {
    int t = blockIdx.x * blockDim.x + threadIdx.x;  // 0..EE-1
    if (t < EE) {
        int r, c;
        if (g_idx64) { r = w[2*t]; c = w[2*EE + 2*t]; }
        else         { r = w[t];   c = w[EE + t]; }
        g_row[t] = r; g_col[t] = c;
    }
    // EE == NN*DD/4 exactly: zero g_sub, copy X -> pre, out[:,0:128] = 2X
    ((float4*)g_sub)[t] = make_float4(0.f, 0.f, 0.f, 0.f);
    float4 x = ((const float4*)X)[t];
    ((float4*)g_pre)[t] = x;
    int node = t >> 5, c4 = (t & 31) << 2;
    *(float4*)(out + (size_t)node*512 + c4) = make_float4(2.f*x.x, 2.f*x.y, 2.f*x.z, 2.f*x.w);
}

__global__ void k_scatter(const float* __restrict__ vals) {
    int t = blockIdx.x * blockDim.x + threadIdx.x;
    int e = t >> 5, d4 = (t & 31) << 2;
    float v = vals[e];
    int r = g_row[e], c = g_col[e];
    float4 p = *(const float4*)(g_pre + (size_t)c*DD + d4);
    float* dst = g_sub + (size_t)r*DD + d4;
    atomicAdd(dst + 0, v*p.x);
    atomicAdd(dst + 1, v*p.y);
    atomicAdd(dst + 2, v*p.z);
    atomicAdd(dst + 3, v*p.w);
}

// split + transpose pre -> g_bT_hi/lo.  grid 128, block 256
__global__ void k_split() {
    int k0 = blockIdx.x * 128;
    int t = threadIdx.x;
#pragma unroll
    for (int l = 0; l < 16; l++) {
        int li = t + l*256;
        int n = li >> 5;            // 0..127
        int ks = (li & 31) * 4;     // 0..124
        float f[4], lo[4];
#pragma unroll
        for (int j = 0; j < 4; j++) {
            f[j] = g_pre[(size_t)(k0 + ks + j)*DD + n];
            float h = __bfloat162float(__float2bfloat16(f[j]));
            lo[j] = f[j] - h;
        }
        uint2 vh = make_uint2(packbf2(f[0], f[1]), packbf2(f[2], f[3]));
        uint2 vl = make_uint2(packbf2(lo[0], lo[1]), packbf2(lo[2], lo[3]));
        *(uint2*)(g_bT_hi + (size_t)n*NN + k0 + ks) = vh;
        *(uint2*)(g_bT_lo + (size_t)n*NN + k0 + ks) = vl;
    }
}

// ---------- mma.sync GEMM: g_all = A @ pre  (M=128/CTA, N=128, KC=32) ----------
#define KC 32
#define PLANE_W (128*AW)          // 3072 words per plane
#define GEMM_SMEM (4*PLANE_W*4)   // 49152 bytes

__global__ void __launch_bounds__(256, 1) k_gemm_mma(const float* __restrict__ A) {
    extern __shared__ uint32_t sm[];
    uint32_t* Ah = sm;
    uint32_t* Al = sm + PLANE_W;
    uint32_t* Bh = sm + 2*PLANE_W;
    uint32_t* Bl = sm + 3*PLANE_W;

    int t = threadIdx.x, lane = t & 31, warp = t >> 5;
    int rb = blockIdx.x * 128;
    int R = warp * 16;                   // warp's row base within tile
    int g4 = lane >> 2;                  // fragment row/col group 0..7
    int kw2 = (lane & 3) * 2;            // fragment k word pair offset

    float acc[16][4];
#pragma unroll
    for (int j = 0; j < 16; j++)
#pragma unroll
        for (int q = 0; q < 4; q++) acc[j][q] = 0.f;

    float4 pa[4];
    uint2  pb[8];

    // ---- load chunk 0 to regs ----
#pragma unroll
    for (int i = 0; i < 4; i++) {
        int li = t + i*256, row = li >> 3, k4 = (li & 7) * 4;
        pa[i] = *(const float4*)(A + (size_t)(rb + row)*NN + k4);
    }
#pragma unroll
    for (int i = 0; i < 8; i++) {
        int li = t + (i & 3)*256, n = li >> 3, k4 = (li & 7) * 4;
        const __nv_bfloat16* src = (i < 4) ? g_bT_hi : g_bT_lo;
        pb[i] = *(const uint2*)(src + (size_t)n*NN + k4);
    }
    // ---- store chunk 0 ----
#pragma unroll
    for (int i = 0; i < 4; i++) {
        int li = t + i*256, row = li >> 3, k4 = (li & 7) * 4;
        float4 v = pa[i];
        float hx = __bfloat162float(__float2bfloat16(v.x));
        float hy = __bfloat162float(__float2bfloat16(v.y));
        float hz = __bfloat162float(__float2bfloat16(v.z));
        float hw = __bfloat162float(__float2bfloat16(v.w));
        int b = row*AW, w0 = WIDX(k4), w1 = WIDX(k4 + 2);
        Ah[b + w0] = packbf2(v.x, v.y);         Ah[b + w1] = packbf2(v.z, v.w);
        Al[b + w0] = packbf2(v.x - hx, v.y - hy); Al[b + w1] = packbf2(v.z - hz, v.w - hw);
    }
#pragma unroll
    for (int i = 0; i < 8; i++) {
        int li = t + (i & 3)*256, n = li >> 3, k4 = (li & 7) * 4;
        uint32_t* dstp = (i < 4) ? Bh : Bl;
        int b = n*AW;
        dstp[b + WIDX(k4)] = pb[i].x;
        dstp[b + WIDX(k4 + 2)] = pb[i].y;
    }
    __syncthreads();

    for (int c = 0; c < NN/KC; c++) {
        int kn = (c + 1) * KC;
        if (kn < NN) {
#pragma unroll
            for (int i = 0; i < 4; i++) {
                int li = t + i*256, row = li >> 3, k4 = (li & 7) * 4;
                pa[i] = *(const float4*)(A + (size_t)(rb + row)*NN + kn + k4);
            }
#pragma unroll
            for (int i = 0; i < 8; i++) {
                int li = t + (i & 3)*256, n = li >> 3, k4 = (li & 7) * 4;
                const __nv_bfloat16* src = (i < 4) ? g_bT_hi : g_bT_lo;
                pb[i] = *(const uint2*)(src + (size_t)n*NN + kn + k4);
            }
        }
        // ---- compute chunk c ----
#pragma unroll
        for (int s = 0; s < 2; s++) {
            int aw0 = (R + g4)*AW + s*8 + kw2;
            uint2 h0 = *(uint2*)&Ah[aw0];
            uint2 h1 = *(uint2*)&Ah[aw0 + 8*AW];
            uint2 l0 = *(uint2*)&Al[aw0];
            uint2 l1 = *(uint2*)&Al[aw0 + 8*AW];
            uint32_t ahi[4] = {h0.x, h1.x, h0.y, h1.y};
            uint32_t alo[4] = {l0.x, l1.x, l0.y, l1.y};
#pragma unroll
            for (int j = 0; j < 16; j++) {
                int bw = (j*8 + g4)*AW + s*8 + kw2;
                uint2 bh = *(uint2*)&Bh[bw];
                uint2 bl = *(uint2*)&Bl[bw];
                mma_bf16(acc[j], ahi, bh.x, bh.y);
                mma_bf16(acc[j], ahi, bl.x, bl.y);
                mma_bf16(acc[j], alo, bh.x, bh.y);
            }
        }
        __syncthreads();
        if (kn < NN) {
#pragma unroll
            for (int i = 0; i < 4; i++) {
                int li = t + i*256, row = li >> 3, k4 = (li & 7) * 4;
                float4 v = pa[i];
                float hx = __bfloat162float(__float2bfloat16(v.x));
                float hy = __bfloat162float(__float2bfloat16(v.y));
                float hz = __bfloat162float(__float2bfloat16(v.z));
                float hw = __bfloat162float(__float2bfloat16(v.w));
                int b = row*AW, w0 = WIDX(k4), w1 = WIDX(k4 + 2);
                Ah[b + w0] = packbf2(v.x, v.y);           Ah[b + w1] = packbf2(v.z, v.w);
                Al[b + w0] = packbf2(v.x - hx, v.y - hy); Al[b + w1] = packbf2(v.z - hz, v.w - hw);
            }
#pragma unroll
            for (int i = 0; i < 8; i++) {
                int li = t + (i & 3)*256, n = li >> 3, k4 = (li & 7) * 4;
                uint32_t* dstp = (i < 4) ? Bh : Bl;
                int b = n*AW;
                dstp[b + WIDX(k4)] = pb[i].x;
                dstp[b + WIDX(k4 + 2)] = pb[i].y;
            }
            __syncthreads();
        }
    }
    // ---- write out ----
    int row0 = rb + R + g4;
#pragma unroll
    for (int j = 0; j < 16; j++) {
        int c0 = j*8 + kw2;
        *(float2*)(g_all + (size_t)row0*DD + c0)       = make_float2(acc[j][0], acc[j][1]);
        *(float2*)(g_all + (size_t)(row0 + 8)*DD + c0) = make_float2(acc[j][2], acc[j][3]);
    }
}

// ---------- fused epilogue ----------
#define WP 132
__global__ void k_epi(const float* __restrict__ W2, const float* __restrict__ b2,
                      const float* __restrict__ W3, const float* __restrict__ b3,
                      float* __restrict__ out, int colOff) {
    extern __shared__ float smf[];
    float* W2s = smf;
    float* W3s = W2s + 128*WP;
    float* as_ = W3s + 128*WP;
    float* ss_ = as_ + 32*WP;
    float* b2s = ss_ + 32*WP;
    float* b3s = b2s + 128;
    int t = threadIdx.x;
#pragma unroll
    for (int l = 0; l < 16; l++) {
        int li = t + l*256, o = li >> 5, d = (li & 31) << 2;
        *(float4*)&W2s[o*WP + d] = *(const float4*)&W2[o*128 + d];
        *(float4*)&W3s[o*WP + d] = *(const float4*)&W3[o*128 + d];
    }
    if (t < 128) { b2s[t] = b2[t]; b3s[t] = b3[t]; }
    int base = blockIdx.x * 32;
#pragma unroll
    for (int l = 0; l < 4; l++) {
        int li = t + l*256, nl = li >> 5, d = (li & 31) << 2;
        size_t g = (size_t)(base + nl)*DD + d;
        float4 p = *(const float4*)(g_pre + g);
        float4 a = *(const float4*)(g_all + g);
        float4 s = *(const float4*)(g_sub + g);
        *(float4*)&as_[nl*WP + d] = make_float4(p.x+a.x, p.y+a.y, p.z+a.z, p.w+a.w);
        *(float4*)&ss_[nl*WP + d] = make_float4(p.x*s.x, p.y*s.y, p.z*s.z, p.w*s.w);
        *(float4*)(g_sub + g) = make_float4(0.f, 0.f, 0.f, 0.f);   // pre-zero for next layer
    }
    __syncthreads();

    int nl = t >> 3, lane8 = t & 7;
    int node = base + nl;
    float acc2[16], acc3[16];
#pragma unroll
    for (int j = 0; j < 16; j++) { acc2[j] = b2s[lane8 + 8*j]; acc3[j] = b3s[lane8 + 8*j]; }
    for (int d4 = 0; d4 < 32; d4++) {
        float4 a = *(float4*)&as_[nl*WP + d4*4];
        float4 s = *(float4*)&ss_[nl*WP + d4*4];
#pragma unroll
        for (int j = 0; j < 16; j++) {
            int o = lane8 + 8*j;
            float4 w2 = *(float4*)&W2s[o*WP + d4*4];
            float4 w3 = *(float4*)&W3s[o*WP + d4*4];
            acc2[j] += a.x*w2.x + a.y*w2.y + a.z*w2.z + a.w*w2.w;
            acc3[j] += s.x*w3.x + s.y*w3.y + s.z*w3.z + s.w*w3.w;
        }
    }
    float emb[16], ssq = 0.f;
#pragma unroll
    for (int j = 0; j < 16; j++) {
        float h2 = acc2[j], h3 = acc3[j];
        float sg = 1.f / (1.f + __expf(-h2));
        float lr = h3 > 0.f ? h3 : 0.01f * h3;
        float e = sg + lr;
        emb[j] = e; ssq += e * e;
    }
    ssq += __shfl_xor_sync(0xffffffffu, ssq, 1);
    ssq += __shfl_xor_sync(0xffffffffu, ssq, 2);
    ssq += __shfl_xor_sync(0xffffffffu, ssq, 4);
    float inv = 1.f / fmaxf(sqrtf(ssq), 1e-12f);
#pragma unroll
    for (int j = 0; j < 16; j++) {
        int o = lane8 + 8*j;
        g_pre[(size_t)node*DD + o] = emb[j];
        out[(size_t)node*512 + colOff + o] = emb[j] * inv;
    }
}

#define EPI_SMEM ((2*128*WP + 2*32*WP + 2*128) * 4)

extern "C" void kernel_launch(void* const* d_in, const int* in_sizes, int n_in,
                              void* d_out, int out_size) {
    const float* A  = (const float*)d_in[0];
    const int*   si = (const int*)d_in[1];
    const float* sv = (const float*)d_in[2];
    const float* X  = (const float*)d_in[3];
    const float* W2 = (const float*)d_in[4];
    const float* b2 = (const float*)d_in[5];
    const float* W3 = (const float*)d_in[6];
    const float* b3 = (const float*)d_in[7];
    float* out = (float*)d_out;

    cudaFuncSetAttribute(k_epi, cudaFuncAttributeMaxDynamicSharedMemorySize, EPI_SMEM);
    cudaFuncSetAttribute(k_gemm_mma, cudaFuncAttributeMaxDynamicSharedMemorySize, GEMM_SMEM);

    k_detect<<<1, 256>>>(si);
    k_init<<<EE/256, 256>>>(si, X, out);
    for (int k = 0; k < 3; k++) {
        k_scatter<<<(EE*32)/256, 256>>>(sv);
        k_split<<<NN/128, 256>>>();
        k_gemm_mma<<<NN/128, 256, GEMM_SMEM>>>(A);
        k_epi<<<NN/32, 256, EPI_SMEM>>>(W2 + k*DD*DD, b2 + k*DD,
                                        W3 + k*DD*DD, b3 + k*DD,
                                        out, (k+1)*DD);
    }
}